// round 2
// baseline (speedup 1.0000x reference)
#include <cuda_runtime.h>

// DDLG autoencoder, fully fused per 8-row group.
// sizes: 4096 -> 2048 -> 1024 -> 2048 -> 4096, batch 4096, NUM_CONN=8.

#define BATCH 4096
#define F0 4096
#define O0 2048
#define O1 1024
#define O2 2048
#define O3 4096
#define TOTAL_O (O0 + O1 + O2 + O3)

#define RPB 8            // rows per block
#define THREADS 512
#define SA 4097          // smem row stride (floats), odd => stride % 32 == 1
#define SB 2049
#define SMEM_BYTES ((RPB * SA + RPB * SB) * 4)

// per-neuron mixing probabilities (softmax(w) or one-hot), precomputed
__device__ float g_probs[TOTAL_O * 4];

__global__ void prob_kernel(const float* __restrict__ w0, const float* __restrict__ w1,
                            const float* __restrict__ w2, const float* __restrict__ w3,
                            const int* __restrict__ is_train) {
    int t = blockIdx.x * blockDim.x + threadIdx.x;
    if (t >= TOTAL_O) return;
    const float* w;
    if (t < O0)                w = w0 + t * 4;
    else if (t < O0 + O1)      w = w1 + (t - O0) * 4;
    else if (t < O0 + O1 + O2) w = w2 + (t - O0 - O1) * 4;
    else                       w = w3 + (t - O0 - O1 - O2) * 4;
    float a = w[0], b = w[1], c = w[2], d = w[3];
    float p0, p1, p2, p3;
    if (*is_train != 0) {
        float m = fmaxf(fmaxf(a, b), fmaxf(c, d));
        float ea = __expf(a - m), eb = __expf(b - m);
        float ec = __expf(c - m), ed = __expf(d - m);
        float inv = __fdividef(1.0f, ea + eb + ec + ed);
        p0 = ea * inv; p1 = eb * inv; p2 = ec * inv; p3 = ed * inv;
    } else {
        int k = 0; float best = a;
        if (b > best) { best = b; k = 1; }
        if (c > best) { best = c; k = 2; }
        if (d > best) { best = d; k = 3; }
        p0 = (k == 0) ? 1.0f : 0.0f;
        p1 = (k == 1) ? 1.0f : 0.0f;
        p2 = (k == 2) ? 1.0f : 0.0f;
        p3 = (k == 3) ? 1.0f : 0.0f;
    }
    *(float4*)(g_probs + t * 4) = make_float4(p0, p1, p2, p3);
}

// One output neuron for one row. ein/coein tracked as rationals:
//   coein: acc=(N+bD)/(D+bN)   -> N'=fma(b,D,N), D'=fma(b,N,D)
//   ein:   acc=Nb/(2D-N+b(N-D))-> N'=N*b,        D'=fma(b,N-D,2D-N)
// Single reciprocal at the end:
//   p2*Ne/De + p3*Nc/Dc = (p2*Ne*Dc + p3*Nc*De) / (De*Dc)
__device__ __forceinline__ float neuron(const float* __restrict__ rowIn,
                                        const int* __restrict__ idxp,
                                        const float* __restrict__ probp) {
    int4 i0 = __ldg((const int4*)idxp);
    int4 i1 = __ldg(((const int4*)idxp) + 1);
    float4 p = __ldg((const float4*)probp);

    float f0 = rowIn[i0.x];
    float f1 = rowIn[i0.y];
    float f2 = rowIn[i0.z];
    float f3 = rowIn[i0.w];
    float f4 = rowIn[i1.x];
    float f5 = rowIn[i1.y];
    float f6 = rowIn[i1.z];
    float f7 = rowIn[i1.w];

    float mn = f0, mx = f0;
    float Ne = f0, De = 1.0f;
    float Nc = f0, Dc = 1.0f;

#define DDLG_STEP(bv)                                   \
    {                                                   \
        float b_ = (bv);                                \
        mn = fminf(mn, b_);                             \
        mx = fmaxf(mx, b_);                             \
        float nDe = fmaf(b_, Ne - De, fmaf(De, 2.0f, -Ne)); \
        Ne = Ne * b_;                                   \
        De = nDe;                                       \
        float nNc = fmaf(b_, Dc, Nc);                   \
        Dc = fmaf(b_, Nc, Dc);                          \
        Nc = nNc;                                       \
    }

    DDLG_STEP(f1) DDLG_STEP(f2) DDLG_STEP(f3) DDLG_STEP(f4)
    DDLG_STEP(f5) DDLG_STEP(f6) DDLG_STEP(f7)
#undef DDLG_STEP

    float num = fmaf(p.z * Ne, Dc, p.w * Nc * De);
    float den = De * Dc;
    return fmaf(p.x, mn, fmaf(p.y, mx, __fdividef(num, den)));
}

// Warp layout: lane = g*8 + r  (r = row 0..7, g = neuron subgroup 0..3).
// With stride % 32 == 1, the 8 lanes of a group hit 8 consecutive banks.
__device__ __forceinline__ void layer(const float* __restrict__ bufIn, int sIn,
                                      float* __restrict__ bufOut, int sOut,
                                      const int* __restrict__ idx,
                                      const float* __restrict__ probs, int O) {
    int lane = threadIdx.x & 31;
    int warp = threadIdx.x >> 5;
    int r = lane & (RPB - 1);
    int g = lane >> 3;
    const float* rowIn = bufIn + r * sIn;
    float* rowOut = bufOut + r * sOut;
    const int stride = (THREADS / 32) * 4;  // 64 neurons per block-iteration
    for (int o = warp * 4 + g; o < O; o += stride) {
        rowOut[o] = neuron(rowIn, idx + o * 8, probs + o * 4);
    }
}

__global__ void __launch_bounds__(THREADS, 1)
ddlg_kernel(const float* __restrict__ x,
            const int* __restrict__ idx0, const int* __restrict__ idx1,
            const int* __restrict__ idx2, const int* __restrict__ idx3,
            float* __restrict__ out) {
    extern __shared__ float sm[];
    float* bufA = sm;                 // up to 4096 cols, stride SA
    float* bufB = sm + RPB * SA;      // up to 2048 cols, stride SB

    const int rowBase = blockIdx.x * RPB;

    // Load 8 contiguous x rows into bufA (coalesced float4).
    const float4* xs = (const float4*)(x + (size_t)rowBase * F0);
    for (int i = threadIdx.x; i < RPB * (F0 / 4); i += THREADS) {
        int r = i >> 10;          // 1024 float4 per row
        int c = i & 1023;
        float4 v = xs[i];
        float* d = bufA + r * SA + c * 4;
        d[0] = v.x; d[1] = v.y; d[2] = v.z; d[3] = v.w;
    }
    __syncthreads();

    layer(bufA, SA, bufB, SB, idx0, g_probs, O0);
    __syncthreads();
    layer(bufB, SB, bufA, SA, idx1, g_probs + O0 * 4, O1);
    __syncthreads();
    layer(bufA, SA, bufB, SB, idx2, g_probs + (O0 + O1) * 4, O2);
    __syncthreads();
    layer(bufB, SB, bufA, SA, idx3, g_probs + (O0 + O1 + O2) * 4, O3);
    __syncthreads();

    // Coalesced float4 store of the final 8 x 4096 tile.
    float4* od = (float4*)(out + (size_t)rowBase * O3);
    for (int i = threadIdx.x; i < RPB * (O3 / 4); i += THREADS) {
        int r = i >> 10;
        int c = i & 1023;
        const float* s = bufA + r * SA + c * 4;
        od[i] = make_float4(s[0], s[1], s[2], s[3]);
    }
}

extern "C" void kernel_launch(void* const* d_in, const int* in_sizes, int n_in,
                              void* d_out, int out_size) {
    const float* x   = (const float*)d_in[0];
    const float* w0  = (const float*)d_in[1];
    const float* w1  = (const float*)d_in[2];
    const float* w2  = (const float*)d_in[3];
    const float* w3  = (const float*)d_in[4];
    const int* idx0  = (const int*)d_in[5];
    const int* idx1  = (const int*)d_in[6];
    const int* idx2  = (const int*)d_in[7];
    const int* idx3  = (const int*)d_in[8];
    const int* is_tr = (const int*)d_in[9];
    float* out = (float*)d_out;

    cudaFuncSetAttribute(ddlg_kernel, cudaFuncAttributeMaxDynamicSharedMemorySize, SMEM_BYTES);

    prob_kernel<<<(TOTAL_O + 255) / 256, 256>>>(w0, w1, w2, w3, is_tr);
    ddlg_kernel<<<BATCH / RPB, THREADS, SMEM_BYTES>>>(x, idx0, idx1, idx2, idx3, out);
}

// round 3
// speedup vs baseline: 1.2710x; 1.2710x over previous
#include <cuda_runtime.h>

// DDLG autoencoder, fully fused per 8-row group.
// sizes: 4096 -> 2048 -> 1024 -> 2048 -> 4096, batch 4096, NUM_CONN=8.

#define BATCH 4096
#define F0 4096
#define O0 2048
#define O1 1024
#define O2 2048
#define O3 4096
#define TOTAL_O (O0 + O1 + O2 + O3)

#define RPB 8            // rows per block
#define THREADS 1024
#define SA 4097          // smem row stride (floats), odd => stride % 32 == 1
#define SB 2049
#define SMEM_BYTES ((RPB * SA + RPB * SB) * 4)

// per-neuron mixing probabilities (softmax(w) or one-hot), precomputed
__device__ float g_probs[TOTAL_O * 4];

__global__ void prob_kernel(const float* __restrict__ w0, const float* __restrict__ w1,
                            const float* __restrict__ w2, const float* __restrict__ w3,
                            const int* __restrict__ is_train) {
    int t = blockIdx.x * blockDim.x + threadIdx.x;
    if (t >= TOTAL_O) return;
    const float* w;
    if (t < O0)                w = w0 + t * 4;
    else if (t < O0 + O1)      w = w1 + (t - O0) * 4;
    else if (t < O0 + O1 + O2) w = w2 + (t - O0 - O1) * 4;
    else                       w = w3 + (t - O0 - O1 - O2) * 4;
    float a = w[0], b = w[1], c = w[2], d = w[3];
    float p0, p1, p2, p3;
    if (*is_train != 0) {
        float m = fmaxf(fmaxf(a, b), fmaxf(c, d));
        float ea = __expf(a - m), eb = __expf(b - m);
        float ec = __expf(c - m), ed = __expf(d - m);
        float inv = __fdividef(1.0f, ea + eb + ec + ed);
        p0 = ea * inv; p1 = eb * inv; p2 = ec * inv; p3 = ed * inv;
    } else {
        int k = 0; float best = a;
        if (b > best) { best = b; k = 1; }
        if (c > best) { best = c; k = 2; }
        if (d > best) { best = d; k = 3; }
        p0 = (k == 0) ? 1.0f : 0.0f;
        p1 = (k == 1) ? 1.0f : 0.0f;
        p2 = (k == 2) ? 1.0f : 0.0f;
        p3 = (k == 3) ? 1.0f : 0.0f;
    }
    *(float4*)(g_probs + t * 4) = make_float4(p0, p1, p2, p3);
}

// One output neuron for one row.
// coein fold as rational:  acc=N/D,  step b: N'=fma(b,D,N), D'=fma(b,N,D).
// ein fold via De Morgan:  ein(...f...) = 1 - coein(...1-f...), so the SAME
// 2-FFMA recurrence on complements u=1-f tracks ein; ein = (Da-Na)/Da.
// Single reciprocal at the end:
//   p2*(Da-Na)/Da + p3*Nc/Dc = (p2*(Da-Na)*Dc + p3*Nc*Da) / (Da*Dc)
__device__ __forceinline__ float neuron(const float* __restrict__ rowIn,
                                        const int* __restrict__ idxp,
                                        const float* __restrict__ probp) {
    int4 i0 = __ldg((const int4*)idxp);
    int4 i1 = __ldg(((const int4*)idxp) + 1);
    float4 p = __ldg((const float4*)probp);

    float f0 = rowIn[i0.x];
    float f1 = rowIn[i0.y];
    float f2 = rowIn[i0.z];
    float f3 = rowIn[i0.w];
    float f4 = rowIn[i1.x];
    float f5 = rowIn[i1.y];
    float f6 = rowIn[i1.z];
    float f7 = rowIn[i1.w];

    float mn = f0, mx = f0;
    float Na = 1.0f - f0, Da = 1.0f;   // ein (on complements)
    float Nc = f0,        Dc = 1.0f;   // coein

#define DDLG_STEP(bv)                                   \
    {                                                   \
        float b_ = (bv);                                \
        mn = fminf(mn, b_);                             \
        mx = fmaxf(mx, b_);                             \
        float u_ = 1.0f - b_;                           \
        float nNa = fmaf(u_, Da, Na);                   \
        Da = fmaf(u_, Na, Da);                          \
        Na = nNa;                                       \
        float nNc = fmaf(b_, Dc, Nc);                   \
        Dc = fmaf(b_, Nc, Dc);                          \
        Nc = nNc;                                       \
    }

    DDLG_STEP(f1) DDLG_STEP(f2) DDLG_STEP(f3) DDLG_STEP(f4)
    DDLG_STEP(f5) DDLG_STEP(f6) DDLG_STEP(f7)
#undef DDLG_STEP

    float ein_num = Da - Na;
    float num = fmaf(p.z * ein_num, Dc, (p.w * Nc) * Da);
    float den = Da * Dc;
    return fmaf(p.x, mn, fmaf(p.y, mx, __fdividef(num, den)));
}

// Warp layout: lane = g*8 + r  (r = row 0..7, g = neuron subgroup 0..3).
// With stride % 32 == 1, the 8 lanes of a group hit 8 consecutive banks.
__device__ __forceinline__ void layer(const float* __restrict__ bufIn, int sIn,
                                      float* __restrict__ bufOut, int sOut,
                                      const int* __restrict__ idx,
                                      const float* __restrict__ probs, int O) {
    int lane = threadIdx.x & 31;
    int warp = threadIdx.x >> 5;
    int r = lane & (RPB - 1);
    int g = lane >> 3;
    const float* rowIn = bufIn + r * sIn;
    float* rowOut = bufOut + r * sOut;
    const int stride = (THREADS / 32) * 4;  // 128 neurons per block-iteration
    #pragma unroll 2
    for (int o = warp * 4 + g; o < O; o += stride) {
        rowOut[o] = neuron(rowIn, idx + o * 8, probs + o * 4);
    }
}

__global__ void __launch_bounds__(THREADS, 1)
ddlg_kernel(const float* __restrict__ x,
            const int* __restrict__ idx0, const int* __restrict__ idx1,
            const int* __restrict__ idx2, const int* __restrict__ idx3,
            float* __restrict__ out) {
    extern __shared__ float sm[];
    float* bufA = sm;                 // up to 4096 cols, stride SA
    float* bufB = sm + RPB * SA;      // up to 2048 cols, stride SB

    const int rowBase = blockIdx.x * RPB;

    // Load 8 contiguous x rows into bufA (coalesced float4).
    const float4* xs = (const float4*)(x + (size_t)rowBase * F0);
    #pragma unroll 4
    for (int i = threadIdx.x; i < RPB * (F0 / 4); i += THREADS) {
        int r = i >> 10;          // 1024 float4 per row
        int c = i & 1023;
        float4 v = xs[i];
        float* d = bufA + r * SA + c * 4;
        d[0] = v.x; d[1] = v.y; d[2] = v.z; d[3] = v.w;
    }
    __syncthreads();

    layer(bufA, SA, bufB, SB, idx0, g_probs, O0);
    __syncthreads();
    layer(bufB, SB, bufA, SA, idx1, g_probs + O0 * 4, O1);
    __syncthreads();
    layer(bufA, SA, bufB, SB, idx2, g_probs + (O0 + O1) * 4, O2);
    __syncthreads();
    layer(bufB, SB, bufA, SA, idx3, g_probs + (O0 + O1 + O2) * 4, O3);
    __syncthreads();

    // Coalesced float4 store of the final 8 x 4096 tile.
    float4* od = (float4*)(out + (size_t)rowBase * O3);
    #pragma unroll 4
    for (int i = threadIdx.x; i < RPB * (O3 / 4); i += THREADS) {
        int r = i >> 10;
        int c = i & 1023;
        const float* s = bufA + r * SA + c * 4;
        od[i] = make_float4(s[0], s[1], s[2], s[3]);
    }
}

extern "C" void kernel_launch(void* const* d_in, const int* in_sizes, int n_in,
                              void* d_out, int out_size) {
    const float* x   = (const float*)d_in[0];
    const float* w0  = (const float*)d_in[1];
    const float* w1  = (const float*)d_in[2];
    const float* w2  = (const float*)d_in[3];
    const float* w3  = (const float*)d_in[4];
    const int* idx0  = (const int*)d_in[5];
    const int* idx1  = (const int*)d_in[6];
    const int* idx2  = (const int*)d_in[7];
    const int* idx3  = (const int*)d_in[8];
    const int* is_tr = (const int*)d_in[9];
    float* out = (float*)d_out;

    cudaFuncSetAttribute(ddlg_kernel, cudaFuncAttributeMaxDynamicSharedMemorySize, SMEM_BYTES);

    prob_kernel<<<(TOTAL_O + 255) / 256, 256>>>(w0, w1, w2, w3, is_tr);
    ddlg_kernel<<<BATCH / RPB, THREADS, SMEM_BYTES>>>(x, idx0, idx1, idx2, idx3, out);
}

// round 4
// speedup vs baseline: 1.7461x; 1.3738x over previous
#include <cuda_runtime.h>
#include <cuda_fp16.h>

// DDLG autoencoder, fully fused. Activations stored in SMEM as half2 packing
// TWO batch rows per 32-bit word; all arithmetic in fp32.
// sizes: 4096 -> 2048 -> 1024 -> 2048 -> 4096, batch 4096, NUM_CONN=8.

#define BATCH 4096
#define F0 4096
#define O0 2048
#define O1 1024
#define O2 2048
#define O3 4096
#define TOTAL_O (O0 + O1 + O2 + O3)

#define RPB 8            // batch rows per block (= 4 row-pairs)
#define THREADS 512
#define S2A 4            // half2 stride per column, buffer A (16B/col)
#define S2B 5            // half2 stride per column, buffer B (20B/col, bank-spread)
#define BUFA_H2 (F0 * S2A)   // 16384 half2 = 64KB
#define BUFB_H2 (O0 * S2B)   // 10240 half2 = 40KB
#define SMEM_BYTES ((BUFA_H2 + BUFB_H2) * 4)   // 104KB -> 2 blocks/SM

// per-neuron mixing probabilities (softmax(w) or one-hot), precomputed
__device__ float g_probs[TOTAL_O * 4];

__global__ void prob_kernel(const float* __restrict__ w0, const float* __restrict__ w1,
                            const float* __restrict__ w2, const float* __restrict__ w3,
                            const int* __restrict__ is_train) {
    int t = blockIdx.x * blockDim.x + threadIdx.x;
    if (t >= TOTAL_O) return;
    const float* w;
    if (t < O0)                w = w0 + t * 4;
    else if (t < O0 + O1)      w = w1 + (t - O0) * 4;
    else if (t < O0 + O1 + O2) w = w2 + (t - O0 - O1) * 4;
    else                       w = w3 + (t - O0 - O1 - O2) * 4;
    float a = w[0], b = w[1], c = w[2], d = w[3];
    float p0, p1, p2, p3;
    if (*is_train != 0) {
        float m = fmaxf(fmaxf(a, b), fmaxf(c, d));
        float ea = __expf(a - m), eb = __expf(b - m);
        float ec = __expf(c - m), ed = __expf(d - m);
        float inv = __fdividef(1.0f, ea + eb + ec + ed);
        p0 = ea * inv; p1 = eb * inv; p2 = ec * inv; p3 = ed * inv;
    } else {
        int k = 0; float best = a;
        if (b > best) { best = b; k = 1; }
        if (c > best) { best = c; k = 2; }
        if (d > best) { best = d; k = 3; }
        p0 = (k == 0) ? 1.0f : 0.0f;
        p1 = (k == 1) ? 1.0f : 0.0f;
        p2 = (k == 2) ? 1.0f : 0.0f;
        p3 = (k == 3) ? 1.0f : 0.0f;
    }
    *(float4*)(g_probs + t * 4) = make_float4(p0, p1, p2, p3);
}

// Dual-row neuron: one lane computes neuron o for two batch rows (packed half2).
// coein fold as rational:  N'=fma(b,D,N), D'=fma(b,N,D).
// ein via De Morgan: ein(f...) = 1 - coein(1-f...); ein = (Da-Na)/Da.
// Single reciprocal per row at the end.
__device__ __forceinline__ float2 neuron2(const __half2* __restrict__ bufIn, int sIn, int rp,
                                          const int* __restrict__ idxp,
                                          const float* __restrict__ probp) {
    int4 i0 = __ldg((const int4*)idxp);
    int4 i1 = __ldg(((const int4*)idxp) + 1);
    float4 p = __ldg((const float4*)probp);

    __half2 h0 = bufIn[i0.x * sIn + rp];
    __half2 h1 = bufIn[i0.y * sIn + rp];
    __half2 h2 = bufIn[i0.z * sIn + rp];
    __half2 h3 = bufIn[i0.w * sIn + rp];
    __half2 h4 = bufIn[i1.x * sIn + rp];
    __half2 h5 = bufIn[i1.y * sIn + rp];
    __half2 h6 = bufIn[i1.z * sIn + rp];
    __half2 h7 = bufIn[i1.w * sIn + rp];

    float2 f = __half22float2(h0);
    float mn0 = f.x, mx0 = f.x, Na0 = 1.0f - f.x, Da0 = 1.0f, Nc0 = f.x, Dc0 = 1.0f;
    float mn1 = f.y, mx1 = f.y, Na1 = 1.0f - f.y, Da1 = 1.0f, Nc1 = f.y, Dc1 = 1.0f;

#define DDLG_STEP(hv)                                       \
    {                                                       \
        float2 fe = __half22float2(hv);                     \
        {                                                   \
            float b_ = fe.x;                                \
            mn0 = fminf(mn0, b_);                           \
            mx0 = fmaxf(mx0, b_);                           \
            float u_ = 1.0f - b_;                           \
            float nNa = fmaf(u_, Da0, Na0);                 \
            Da0 = fmaf(u_, Na0, Da0);                       \
            Na0 = nNa;                                      \
            float nNc = fmaf(b_, Dc0, Nc0);                 \
            Dc0 = fmaf(b_, Nc0, Dc0);                       \
            Nc0 = nNc;                                      \
        }                                                   \
        {                                                   \
            float b_ = fe.y;                                \
            mn1 = fminf(mn1, b_);                           \
            mx1 = fmaxf(mx1, b_);                           \
            float u_ = 1.0f - b_;                           \
            float nNa = fmaf(u_, Da1, Na1);                 \
            Da1 = fmaf(u_, Na1, Da1);                       \
            Na1 = nNa;                                      \
            float nNc = fmaf(b_, Dc1, Nc1);                 \
            Dc1 = fmaf(b_, Nc1, Dc1);                       \
            Nc1 = nNc;                                      \
        }                                                   \
    }

    DDLG_STEP(h1) DDLG_STEP(h2) DDLG_STEP(h3) DDLG_STEP(h4)
    DDLG_STEP(h5) DDLG_STEP(h6) DDLG_STEP(h7)
#undef DDLG_STEP

    float e0 = Da0 - Na0;
    float num0 = fmaf(p.z * e0, Dc0, (p.w * Nc0) * Da0);
    float r0 = fmaf(p.x, mn0, fmaf(p.y, mx0, __fdividef(num0, Da0 * Dc0)));
    float e1 = Da1 - Na1;
    float num1 = fmaf(p.z * e1, Dc1, (p.w * Nc1) * Da1);
    float r1 = fmaf(p.x, mn1, fmaf(p.y, mx1, __fdividef(num1, Da1 * Dc1)));
    return make_float2(r0, r1);
}

// Warp layout: lane = g*4 + rp  (rp = row-pair 0..3, g = neuron subgroup 0..7).
__device__ __forceinline__ void layer2(const __half2* __restrict__ bufIn, int sIn,
                                       __half2* __restrict__ bufOut, int sOut,
                                       const int* __restrict__ idx,
                                       const float* __restrict__ probs, int O) {
    int lane = threadIdx.x & 31;
    int warp = threadIdx.x >> 5;
    int rp = lane & 3;
    int g = lane >> 2;
    const int stride = (THREADS / 32) * 8;  // 128 neurons per block-iteration
    for (int o = warp * 8 + g; o < O; o += stride) {
        float2 r = neuron2(bufIn, sIn, rp, idx + o * 8, probs + o * 4);
        bufOut[o * sOut + rp] = __floats2half2_rn(r.x, r.y);
    }
}

__global__ void __launch_bounds__(THREADS, 2)
ddlg_kernel(const float* __restrict__ x,
            const int* __restrict__ idx0, const int* __restrict__ idx1,
            const int* __restrict__ idx2, const int* __restrict__ idx3,
            float* __restrict__ out) {
    extern __shared__ __half2 sm2[];
    __half2* bufA = sm2;               // stride S2A, up to 4096 cols
    __half2* bufB = sm2 + BUFA_H2;     // stride S2B, up to 2048 cols

    const int rowBase = blockIdx.x * RPB;
    const int lane = threadIdx.x & 31;
    const int warp = threadIdx.x >> 5;

    // Load 8 rows of x, transpose into row-pair half2 layout.
    // lane = rpl*8 + cc: loads float4 chunks of rows 2*rpl, 2*rpl+1.
    {
        int rpl = lane >> 3;
        int cc = lane & 7;
        const float4* xs = (const float4*)(x + (size_t)rowBase * F0);
        #pragma unroll
        for (int c4 = warp * 8 + cc; c4 < F0 / 4; c4 += (THREADS / 32) * 8) {
            float4 a = xs[(2 * rpl) * (F0 / 4) + c4];
            float4 b = xs[(2 * rpl + 1) * (F0 / 4) + c4];
            int c = c4 * 4;
            bufA[(c + 0) * S2A + rpl] = __floats2half2_rn(a.x, b.x);
            bufA[(c + 1) * S2A + rpl] = __floats2half2_rn(a.y, b.y);
            bufA[(c + 2) * S2A + rpl] = __floats2half2_rn(a.z, b.z);
            bufA[(c + 3) * S2A + rpl] = __floats2half2_rn(a.w, b.w);
        }
    }
    __syncthreads();

    layer2(bufA, S2A, bufB, S2B, idx0, g_probs, O0);
    __syncthreads();
    layer2(bufB, S2B, bufA, S2A, idx1, g_probs + O0 * 4, O1);
    __syncthreads();
    layer2(bufA, S2A, bufB, S2B, idx2, g_probs + (O0 + O1) * 4, O2);
    __syncthreads();
    layer2(bufB, S2B, bufA, S2A, idx3, g_probs + (O0 + O1 + O2) * 4, O3);
    __syncthreads();

    // Final store: un-pair bufA (4096 cols) into coalesced fp32 rows.
    {
        int rpl = lane >> 3;
        int cc = lane & 7;
        float4* od = (float4*)(out + (size_t)rowBase * O3);
        #pragma unroll
        for (int c4 = warp * 8 + cc; c4 < O3 / 4; c4 += (THREADS / 32) * 8) {
            int c = c4 * 4;
            float2 v0 = __half22float2(bufA[(c + 0) * S2A + rpl]);
            float2 v1 = __half22float2(bufA[(c + 1) * S2A + rpl]);
            float2 v2 = __half22float2(bufA[(c + 2) * S2A + rpl]);
            float2 v3 = __half22float2(bufA[(c + 3) * S2A + rpl]);
            od[(2 * rpl) * (O3 / 4) + c4]     = make_float4(v0.x, v1.x, v2.x, v3.x);
            od[(2 * rpl + 1) * (O3 / 4) + c4] = make_float4(v0.y, v1.y, v2.y, v3.y);
        }
    }
}

extern "C" void kernel_launch(void* const* d_in, const int* in_sizes, int n_in,
                              void* d_out, int out_size) {
    const float* x   = (const float*)d_in[0];
    const float* w0  = (const float*)d_in[1];
    const float* w1  = (const float*)d_in[2];
    const float* w2  = (const float*)d_in[3];
    const float* w3  = (const float*)d_in[4];
    const int* idx0  = (const int*)d_in[5];
    const int* idx1  = (const int*)d_in[6];
    const int* idx2  = (const int*)d_in[7];
    const int* idx3  = (const int*)d_in[8];
    const int* is_tr = (const int*)d_in[9];
    float* out = (float*)d_out;

    cudaFuncSetAttribute(ddlg_kernel, cudaFuncAttributeMaxDynamicSharedMemorySize, SMEM_BYTES);

    prob_kernel<<<(TOTAL_O + 255) / 256, 256>>>(w0, w1, w2, w3, is_tr);
    ddlg_kernel<<<BATCH / RPB, THREADS, SMEM_BYTES>>>(x, idx0, idx1, idx2, idx3, out);
}

// round 5
// speedup vs baseline: 1.8807x; 1.0771x over previous
#include <cuda_runtime.h>
#include <cuda_fp16.h>

// DDLG autoencoder, fully fused. Activations stored in SMEM as half2 packing
// TWO batch rows per 32-bit word; rational recurrences in fp32, min/max in half2.
// sizes: 4096 -> 2048 -> 1024 -> 2048 -> 4096, batch 4096, NUM_CONN=8.

#define BATCH 4096
#define F0 4096
#define O0 2048
#define O1 1024
#define O2 2048
#define O3 4096
#define TOTAL_O (O0 + O1 + O2 + O3)

#define RPB 8            // batch rows per block (= 4 row-pairs)
#define THREADS 640
#define NWARP (THREADS / 32)
#define S2A 4            // half2 stride per column, buffer A (16B/col)
#define S2B 5            // half2 stride per column, buffer B (20B/col, bank-spread)
#define BUFA_H2 (F0 * S2A)   // 16384 half2 = 64KB
#define BUFB_H2 (O0 * S2B)   // 10240 half2 = 40KB
#define SMEM_BYTES ((BUFA_H2 + BUFB_H2) * 4)   // 104KB -> 2 blocks/SM

// per-neuron mixing probabilities (softmax(w) or one-hot), precomputed
__device__ float g_probs[TOTAL_O * 4];

__global__ void prob_kernel(const float* __restrict__ w0, const float* __restrict__ w1,
                            const float* __restrict__ w2, const float* __restrict__ w3,
                            const int* __restrict__ is_train) {
    int t = blockIdx.x * blockDim.x + threadIdx.x;
    if (t >= TOTAL_O) return;
    const float* w;
    if (t < O0)                w = w0 + t * 4;
    else if (t < O0 + O1)      w = w1 + (t - O0) * 4;
    else if (t < O0 + O1 + O2) w = w2 + (t - O0 - O1) * 4;
    else                       w = w3 + (t - O0 - O1 - O2) * 4;
    float a = w[0], b = w[1], c = w[2], d = w[3];
    float p0, p1, p2, p3;
    if (*is_train != 0) {
        float m = fmaxf(fmaxf(a, b), fmaxf(c, d));
        float ea = __expf(a - m), eb = __expf(b - m);
        float ec = __expf(c - m), ed = __expf(d - m);
        float inv = __fdividef(1.0f, ea + eb + ec + ed);
        p0 = ea * inv; p1 = eb * inv; p2 = ec * inv; p3 = ed * inv;
    } else {
        int k = 0; float best = a;
        if (b > best) { best = b; k = 1; }
        if (c > best) { best = c; k = 2; }
        if (d > best) { best = d; k = 3; }
        p0 = (k == 0) ? 1.0f : 0.0f;
        p1 = (k == 1) ? 1.0f : 0.0f;
        p2 = (k == 2) ? 1.0f : 0.0f;
        p3 = (k == 3) ? 1.0f : 0.0f;
    }
    *(float4*)(g_probs + t * 4) = make_float4(p0, p1, p2, p3);
}

// Dual-row neuron: one lane computes neuron o for two batch rows (packed half2).
// coein fold as rational:  N'=fma(b,D,N), D'=fma(b,N,D).
// ein via De Morgan: ein(f...) = 1 - coein(1-f...); ein = (Da-Na)/Da.
// min/max folded in half2 SIMD (exact). Single reciprocal per row at the end.
__device__ __forceinline__ float2 neuron2(const __half2* __restrict__ bufIn, int sIn, int rp,
                                          const int* __restrict__ idxp,
                                          const float* __restrict__ probp) {
    int4 i0 = __ldg((const int4*)idxp);
    int4 i1 = __ldg(((const int4*)idxp) + 1);
    float4 p = __ldg((const float4*)probp);

    __half2 h0 = bufIn[i0.x * sIn + rp];
    __half2 h1 = bufIn[i0.y * sIn + rp];
    __half2 h2 = bufIn[i0.z * sIn + rp];
    __half2 h3 = bufIn[i0.w * sIn + rp];
    __half2 h4 = bufIn[i1.x * sIn + rp];
    __half2 h5 = bufIn[i1.y * sIn + rp];
    __half2 h6 = bufIn[i1.z * sIn + rp];
    __half2 h7 = bufIn[i1.w * sIn + rp];

    __half2 mnh = h0, mxh = h0;
    float2 f = __half22float2(h0);
    float Na0 = 1.0f - f.x, Da0 = 1.0f, Nc0 = f.x, Dc0 = 1.0f;
    float Na1 = 1.0f - f.y, Da1 = 1.0f, Nc1 = f.y, Dc1 = 1.0f;

#define DDLG_STEP(hv)                                       \
    {                                                       \
        mnh = __hmin2(mnh, hv);                             \
        mxh = __hmax2(mxh, hv);                             \
        float2 fe = __half22float2(hv);                     \
        {                                                   \
            float b_ = fe.x;                                \
            float u_ = 1.0f - b_;                           \
            float nNa = fmaf(u_, Da0, Na0);                 \
            Da0 = fmaf(u_, Na0, Da0);                       \
            Na0 = nNa;                                      \
            float nNc = fmaf(b_, Dc0, Nc0);                 \
            Dc0 = fmaf(b_, Nc0, Dc0);                       \
            Nc0 = nNc;                                      \
        }                                                   \
        {                                                   \
            float b_ = fe.y;                                \
            float u_ = 1.0f - b_;                           \
            float nNa = fmaf(u_, Da1, Na1);                 \
            Da1 = fmaf(u_, Na1, Da1);                       \
            Na1 = nNa;                                      \
            float nNc = fmaf(b_, Dc1, Nc1);                 \
            Dc1 = fmaf(b_, Nc1, Dc1);                       \
            Nc1 = nNc;                                      \
        }                                                   \
    }

    DDLG_STEP(h1) DDLG_STEP(h2) DDLG_STEP(h3) DDLG_STEP(h4)
    DDLG_STEP(h5) DDLG_STEP(h6) DDLG_STEP(h7)
#undef DDLG_STEP

    float2 mnf = __half22float2(mnh);
    float2 mxf = __half22float2(mxh);

    float e0 = Da0 - Na0;
    float num0 = fmaf(p.z * e0, Dc0, (p.w * Nc0) * Da0);
    float r0 = fmaf(p.x, mnf.x, fmaf(p.y, mxf.x, __fdividef(num0, Da0 * Dc0)));
    float e1 = Da1 - Na1;
    float num1 = fmaf(p.z * e1, Dc1, (p.w * Nc1) * Da1);
    float r1 = fmaf(p.x, mnf.y, fmaf(p.y, mxf.y, __fdividef(num1, Da1 * Dc1)));
    return make_float2(r0, r1);
}

// Warp layout: lane = g*4 + rp  (rp = row-pair 0..3, g = neuron subgroup 0..7).
__device__ __forceinline__ void layer2(const __half2* __restrict__ bufIn, int sIn,
                                       __half2* __restrict__ bufOut, int sOut,
                                       const int* __restrict__ idx,
                                       const float* __restrict__ probs, int O) {
    int lane = threadIdx.x & 31;
    int warp = threadIdx.x >> 5;
    int rp = lane & 3;
    int g = lane >> 2;
    const int stride = NWARP * 8;  // neurons per block-iteration
    for (int o = warp * 8 + g; o < O; o += stride) {
        float2 r = neuron2(bufIn, sIn, rp, idx + o * 8, probs + o * 4);
        bufOut[o * sOut + rp] = __floats2half2_rn(r.x, r.y);
    }
}

__global__ void __launch_bounds__(THREADS, 2)
ddlg_kernel(const float* __restrict__ x,
            const int* __restrict__ idx0, const int* __restrict__ idx1,
            const int* __restrict__ idx2, const int* __restrict__ idx3,
            float* __restrict__ out) {
    extern __shared__ __half2 sm2[];
    __half2* bufA = sm2;               // stride S2A, up to 4096 cols
    __half2* bufB = sm2 + BUFA_H2;     // stride S2B, up to 2048 cols

    const int rowBase = blockIdx.x * RPB;
    const int lane = threadIdx.x & 31;
    const int warp = threadIdx.x >> 5;

    // Load 8 rows of x, transpose into row-pair half2 layout.
    // lane = rpl*8 + cc: loads float4 chunks of rows 2*rpl, 2*rpl+1.
    {
        int rpl = lane >> 3;
        int cc = lane & 7;
        const float4* xs = (const float4*)(x + (size_t)rowBase * F0);
        for (int c4 = warp * 8 + cc; c4 < F0 / 4; c4 += NWARP * 8) {
            float4 a = xs[(2 * rpl) * (F0 / 4) + c4];
            float4 b = xs[(2 * rpl + 1) * (F0 / 4) + c4];
            int c = c4 * 4;
            bufA[(c + 0) * S2A + rpl] = __floats2half2_rn(a.x, b.x);
            bufA[(c + 1) * S2A + rpl] = __floats2half2_rn(a.y, b.y);
            bufA[(c + 2) * S2A + rpl] = __floats2half2_rn(a.z, b.z);
            bufA[(c + 3) * S2A + rpl] = __floats2half2_rn(a.w, b.w);
        }
    }
    __syncthreads();

    layer2(bufA, S2A, bufB, S2B, idx0, g_probs, O0);
    __syncthreads();
    layer2(bufB, S2B, bufA, S2A, idx1, g_probs + O0 * 4, O1);
    __syncthreads();
    layer2(bufA, S2A, bufB, S2B, idx2, g_probs + (O0 + O1) * 4, O2);
    __syncthreads();
    layer2(bufB, S2B, bufA, S2A, idx3, g_probs + (O0 + O1 + O2) * 4, O3);
    __syncthreads();

    // Final store: un-pair bufA (4096 cols) into coalesced fp32 rows.
    {
        int rpl = lane >> 3;
        int cc = lane & 7;
        float4* od = (float4*)(out + (size_t)rowBase * O3);
        for (int c4 = warp * 8 + cc; c4 < O3 / 4; c4 += NWARP * 8) {
            int c = c4 * 4;
            float2 v0 = __half22float2(bufA[(c + 0) * S2A + rpl]);
            float2 v1 = __half22float2(bufA[(c + 1) * S2A + rpl]);
            float2 v2 = __half22float2(bufA[(c + 2) * S2A + rpl]);
            float2 v3 = __half22float2(bufA[(c + 3) * S2A + rpl]);
            od[(2 * rpl) * (O3 / 4) + c4]     = make_float4(v0.x, v1.x, v2.x, v3.x);
            od[(2 * rpl + 1) * (O3 / 4) + c4] = make_float4(v0.y, v1.y, v2.y, v3.y);
        }
    }
}

extern "C" void kernel_launch(void* const* d_in, const int* in_sizes, int n_in,
                              void* d_out, int out_size) {
    const float* x   = (const float*)d_in[0];
    const float* w0  = (const float*)d_in[1];
    const float* w1  = (const float*)d_in[2];
    const float* w2  = (const float*)d_in[3];
    const float* w3  = (const float*)d_in[4];
    const int* idx0  = (const int*)d_in[5];
    const int* idx1  = (const int*)d_in[6];
    const int* idx2  = (const int*)d_in[7];
    const int* idx3  = (const int*)d_in[8];
    const int* is_tr = (const int*)d_in[9];
    float* out = (float*)d_out;

    cudaFuncSetAttribute(ddlg_kernel, cudaFuncAttributeMaxDynamicSharedMemorySize, SMEM_BYTES);

    prob_kernel<<<(TOTAL_O + 255) / 256, 256>>>(w0, w1, w2, w3, is_tr);
    ddlg_kernel<<<BATCH / RPB, THREADS, SMEM_BYTES>>>(x, idx0, idx1, idx2, idx3, out);
}